// round 1
// baseline (speedup 1.0000x reference)
#include <cuda_runtime.h>
#include <math.h>

// Problem constants
#define Bc  2
#define Sc  2048
#define Dc  1024
#define Hc  16
#define DKc 64
#define Mc  (Bc * Sc)   // 4096 rows for the projection GEMMs

// -------- device scratch (no cudaMalloc allowed) --------
__device__ float g_Q[Mc * Dc];
__device__ float g_K[Mc * Dc];
__device__ float g_V[Mc * Dc];
__device__ float g_C[Mc * Dc];

// ============================================================
// GEMM: C[M=4096, N=1024] = A[M,1024] * W[1024,1024] + bias[N]
// 128x128 block tile, BK=8, 256 threads, 8x8 microtile.
// ============================================================
#define GBM 128
#define GBN 128
#define GBK 8
#define GTM 8
#define GTN 8

__global__ __launch_bounds__(256, 2)
void gemm_bias_kernel(const float* __restrict__ A,
                      const float* __restrict__ W,
                      const float* __restrict__ bias,
                      float* __restrict__ C)
{
    __shared__ float As[GBK][GBM];
    __shared__ float Bs[GBK][GBN];

    const int tid  = threadIdx.x;
    const int row0 = blockIdx.y * GBM;
    const int col0 = blockIdx.x * GBN;

    // A tile load: 128 rows x 8 k = 256 float4 (2 per row)
    const int arow = tid >> 1;
    const int acol = (tid & 1) * 4;
    // B tile load: 8 rows x 128 cols = 256 float4
    const int brow = tid >> 5;
    const int bcol = (tid & 31) * 4;

    const int ty = tid >> 4;   // 0..15
    const int tx = tid & 15;   // 0..15

    float acc[GTM][GTN];
#pragma unroll
    for (int i = 0; i < GTM; i++)
#pragma unroll
        for (int j = 0; j < GTN; j++) acc[i][j] = 0.f;

    for (int k0 = 0; k0 < Dc; k0 += GBK) {
        float4 av = *reinterpret_cast<const float4*>(
            &A[(size_t)(row0 + arow) * Dc + k0 + acol]);
        As[acol + 0][arow] = av.x;
        As[acol + 1][arow] = av.y;
        As[acol + 2][arow] = av.z;
        As[acol + 3][arow] = av.w;
        *reinterpret_cast<float4*>(&Bs[brow][bcol]) =
            *reinterpret_cast<const float4*>(
                &W[(size_t)(k0 + brow) * Dc + col0 + bcol]);
        __syncthreads();

#pragma unroll
        for (int kk = 0; kk < GBK; kk++) {
            float afr[GTM], bfr[GTN];
#pragma unroll
            for (int i = 0; i < GTM; i += 4) {
                float4 t = *reinterpret_cast<const float4*>(&As[kk][ty * GTM + i]);
                afr[i] = t.x; afr[i + 1] = t.y; afr[i + 2] = t.z; afr[i + 3] = t.w;
            }
#pragma unroll
            for (int j = 0; j < GTN; j += 4) {
                float4 t = *reinterpret_cast<const float4*>(&Bs[kk][tx * GTN + j]);
                bfr[j] = t.x; bfr[j + 1] = t.y; bfr[j + 2] = t.z; bfr[j + 3] = t.w;
            }
#pragma unroll
            for (int i = 0; i < GTM; i++)
#pragma unroll
                for (int j = 0; j < GTN; j++)
                    acc[i][j] = fmaf(afr[i], bfr[j], acc[i][j]);
        }
        __syncthreads();
    }

#pragma unroll
    for (int i = 0; i < GTM; i++) {
        const int r = row0 + ty * GTM + i;
#pragma unroll
        for (int j = 0; j < GTN; j += 4) {
            const int c = col0 + tx * GTN + j;
            float4 o;
            o.x = acc[i][j + 0] + bias[c + 0];
            o.y = acc[i][j + 1] + bias[c + 1];
            o.z = acc[i][j + 2] + bias[c + 2];
            o.w = acc[i][j + 3] + bias[c + 3];
            *reinterpret_cast<float4*>(&C[(size_t)r * Dc + c]) = o;
        }
    }
}

// ============================================================
// Causal flash attention, fp32.
// Block = (b, h, 64-query tile). 256 threads = 16x16, 4x4 microtiles.
// Online softmax over 64-wide KV tiles; skips fully-masked tiles.
// ============================================================
#define AQ 64
#define AJ 64

struct AttnSmem {
    float Qs[AQ][DKc + 1];   // [q][k]   (pad 65 -> column reads 2-way max)
    float Ks[AJ][DKc + 1];   // [j][k]
    float Ps[AQ][AJ + 1];    // [q][j]
    float Vs[AJ][DKc];       // [j][dk]  row-major float4 reads, no pad needed
};

__global__ __launch_bounds__(256, 3)
void attn_kernel()
{
    extern __shared__ char smem_raw[];
    AttnSmem& sm = *reinterpret_cast<AttnSmem*>(smem_raw);

    const int qt = blockIdx.x;   // 0..31
    const int h  = blockIdx.y;   // 0..15
    const int b  = blockIdx.z;   // 0..1
    const int q0 = qt * AQ;

    const int tid = threadIdx.x;
    const int ty  = tid >> 4;     // 0..15
    const int tx  = tid & 15;     // 0..15
    const int qrow = ty * 4;
    const int jcol = tx * 4;

    // tile-load mapping: 4 float4 per thread
    const int lrow = tid >> 4;          // 0..15 (+16 per iter)
    const int lcol = (tid & 15) * 4;    // 0..60

    // load Q tile once
#pragma unroll
    for (int it = 0; it < 4; it++) {
        const int r = lrow + it * 16;
        float4 v = *reinterpret_cast<const float4*>(
            &g_Q[(size_t)(b * Sc + q0 + r) * Dc + h * DKc + lcol]);
        sm.Qs[r][lcol + 0] = v.x;
        sm.Qs[r][lcol + 1] = v.y;
        sm.Qs[r][lcol + 2] = v.z;
        sm.Qs[r][lcol + 3] = v.w;
    }

    float m[4], l[4], o[4][4];
#pragma unroll
    for (int i = 0; i < 4; i++) {
        m[i] = -1e30f;
        l[i] = 0.f;
#pragma unroll
        for (int j = 0; j < 4; j++) o[i][j] = 0.f;
    }

    for (int j0 = 0; j0 <= q0; j0 += AJ) {
        __syncthreads();   // protect Ks/Vs from previous iteration's readers
        // load K and V tiles
#pragma unroll
        for (int it = 0; it < 4; it++) {
            const int r = lrow + it * 16;
            float4 kv = *reinterpret_cast<const float4*>(
                &g_K[(size_t)(b * Sc + j0 + r) * Dc + h * DKc + lcol]);
            sm.Ks[r][lcol + 0] = kv.x;
            sm.Ks[r][lcol + 1] = kv.y;
            sm.Ks[r][lcol + 2] = kv.z;
            sm.Ks[r][lcol + 3] = kv.w;
            *reinterpret_cast<float4*>(&sm.Vs[r][lcol]) =
                *reinterpret_cast<const float4*>(
                    &g_V[(size_t)(b * Sc + j0 + r) * Dc + h * DKc + lcol]);
        }
        __syncthreads();

        // GEMM1: S = Q * K^T  (4x4 per thread)
        float s[4][4];
#pragma unroll
        for (int i = 0; i < 4; i++)
#pragma unroll
            for (int j = 0; j < 4; j++) s[i][j] = 0.f;

#pragma unroll 8
        for (int kk = 0; kk < DKc; kk++) {
            float a0 = sm.Qs[qrow + 0][kk];
            float a1 = sm.Qs[qrow + 1][kk];
            float a2 = sm.Qs[qrow + 2][kk];
            float a3 = sm.Qs[qrow + 3][kk];
            float b0 = sm.Ks[jcol + 0][kk];
            float b1 = sm.Ks[jcol + 1][kk];
            float b2 = sm.Ks[jcol + 2][kk];
            float b3 = sm.Ks[jcol + 3][kk];
            s[0][0] = fmaf(a0, b0, s[0][0]); s[0][1] = fmaf(a0, b1, s[0][1]);
            s[0][2] = fmaf(a0, b2, s[0][2]); s[0][3] = fmaf(a0, b3, s[0][3]);
            s[1][0] = fmaf(a1, b0, s[1][0]); s[1][1] = fmaf(a1, b1, s[1][1]);
            s[1][2] = fmaf(a1, b2, s[1][2]); s[1][3] = fmaf(a1, b3, s[1][3]);
            s[2][0] = fmaf(a2, b0, s[2][0]); s[2][1] = fmaf(a2, b1, s[2][1]);
            s[2][2] = fmaf(a2, b2, s[2][2]); s[2][3] = fmaf(a2, b3, s[2][3]);
            s[3][0] = fmaf(a3, b0, s[3][0]); s[3][1] = fmaf(a3, b1, s[3][1]);
            s[3][2] = fmaf(a3, b2, s[3][2]); s[3][3] = fmaf(a3, b3, s[3][3]);
        }

        const float scale = 0.125f;   // 1/sqrt(64)
#pragma unroll
        for (int i = 0; i < 4; i++)
#pragma unroll
            for (int j = 0; j < 4; j++) s[i][j] *= scale;

        // causal mask only on the diagonal tile
        if (j0 == q0) {
#pragma unroll
            for (int i = 0; i < 4; i++) {
                const int gq = q0 + qrow + i;
#pragma unroll
                for (int j = 0; j < 4; j++) {
                    const int gk = j0 + jcol + j;
                    if (gk > gq) s[i][j] = -1e9f;
                }
            }
        }

        // online softmax per query row (row spread across 16 tx threads)
#pragma unroll
        for (int i = 0; i < 4; i++) {
            float mx = fmaxf(fmaxf(s[i][0], s[i][1]), fmaxf(s[i][2], s[i][3]));
#pragma unroll
            for (int off = 8; off >= 1; off >>= 1)
                mx = fmaxf(mx, __shfl_xor_sync(0xffffffffu, mx, off, 16));
            const float mnew  = fmaxf(m[i], mx);
            const float alpha = __expf(m[i] - mnew);
            float p0 = __expf(s[i][0] - mnew);
            float p1 = __expf(s[i][1] - mnew);
            float p2 = __expf(s[i][2] - mnew);
            float p3 = __expf(s[i][3] - mnew);
            float rs = p0 + p1 + p2 + p3;
#pragma unroll
            for (int off = 8; off >= 1; off >>= 1)
                rs += __shfl_xor_sync(0xffffffffu, rs, off, 16);
            l[i] = l[i] * alpha + rs;
            m[i] = mnew;
            o[i][0] *= alpha; o[i][1] *= alpha; o[i][2] *= alpha; o[i][3] *= alpha;
            sm.Ps[qrow + i][jcol + 0] = p0;
            sm.Ps[qrow + i][jcol + 1] = p1;
            sm.Ps[qrow + i][jcol + 2] = p2;
            sm.Ps[qrow + i][jcol + 3] = p3;
        }
        __syncthreads();

        // GEMM2: O += P * V
#pragma unroll 8
        for (int jj = 0; jj < AJ; jj++) {
            float a0 = sm.Ps[qrow + 0][jj];
            float a1 = sm.Ps[qrow + 1][jj];
            float a2 = sm.Ps[qrow + 2][jj];
            float a3 = sm.Ps[qrow + 3][jj];
            float4 bv = *reinterpret_cast<const float4*>(&sm.Vs[jj][jcol]);
            o[0][0] = fmaf(a0, bv.x, o[0][0]); o[0][1] = fmaf(a0, bv.y, o[0][1]);
            o[0][2] = fmaf(a0, bv.z, o[0][2]); o[0][3] = fmaf(a0, bv.w, o[0][3]);
            o[1][0] = fmaf(a1, bv.x, o[1][0]); o[1][1] = fmaf(a1, bv.y, o[1][1]);
            o[1][2] = fmaf(a1, bv.z, o[1][2]); o[1][3] = fmaf(a1, bv.w, o[1][3]);
            o[2][0] = fmaf(a2, bv.x, o[2][0]); o[2][1] = fmaf(a2, bv.y, o[2][1]);
            o[2][2] = fmaf(a2, bv.z, o[2][2]); o[2][3] = fmaf(a2, bv.w, o[2][3]);
            o[3][0] = fmaf(a3, bv.x, o[3][0]); o[3][1] = fmaf(a3, bv.y, o[3][1]);
            o[3][2] = fmaf(a3, bv.z, o[3][2]); o[3][3] = fmaf(a3, bv.w, o[3][3]);
        }
    }

    // normalize + write context tile
#pragma unroll
    for (int i = 0; i < 4; i++) {
        const float inv = 1.0f / l[i];
        float4 ov;
        ov.x = o[i][0] * inv;
        ov.y = o[i][1] * inv;
        ov.z = o[i][2] * inv;
        ov.w = o[i][3] * inv;
        *reinterpret_cast<float4*>(
            &g_C[(size_t)(b * Sc + q0 + qrow + i) * Dc + h * DKc + jcol]) = ov;
    }
}

// ============================================================
// launch
// ============================================================
extern "C" void kernel_launch(void* const* d_in, const int* in_sizes, int n_in,
                              void* d_out, int out_size)
{
    (void)in_sizes; (void)n_in; (void)out_size;
    const float* q  = (const float*)d_in[0];
    const float* k  = (const float*)d_in[1];
    const float* v  = (const float*)d_in[2];
    // d_in[3] = mask (causal tril, implemented analytically)
    const float* wq = (const float*)d_in[4];
    const float* bq = (const float*)d_in[5];
    const float* wk = (const float*)d_in[6];
    const float* bk = (const float*)d_in[7];
    const float* wv = (const float*)d_in[8];
    const float* bv = (const float*)d_in[9];
    const float* wo = (const float*)d_in[10];
    const float* bo = (const float*)d_in[11];
    float* out = (float*)d_out;

    float *pQ, *pK, *pV, *pC;
    cudaGetSymbolAddress((void**)&pQ, g_Q);
    cudaGetSymbolAddress((void**)&pK, g_K);
    cudaGetSymbolAddress((void**)&pV, g_V);
    cudaGetSymbolAddress((void**)&pC, g_C);

    dim3 ggrid(Dc / GBN, Mc / GBM);   // (8, 32)
    gemm_bias_kernel<<<ggrid, 256>>>(q, wq, bq, pQ);
    gemm_bias_kernel<<<ggrid, 256>>>(k, wk, bk, pK);
    gemm_bias_kernel<<<ggrid, 256>>>(v, wv, bv, pV);

    cudaFuncSetAttribute(attn_kernel,
                         cudaFuncAttributeMaxDynamicSharedMemorySize,
                         (int)sizeof(AttnSmem));
    dim3 agrid(Sc / AQ, Hc, Bc);      // (32, 16, 2)
    attn_kernel<<<agrid, 256, sizeof(AttnSmem)>>>();

    gemm_bias_kernel<<<ggrid, 256>>>(pC, wo, bo, out);
}

// round 6
// speedup vs baseline: 1.3159x; 1.3159x over previous
#include <cuda_runtime.h>
#include <cuda_bf16.h>
#include <mma.h>
#include <math.h>

using namespace nvcuda;

// Problem constants
#define Bc  2
#define Sc  2048
#define Dc  1024
#define Hc  16
#define DKc 64
#define Mc  (Bc * Sc)

// -------- device scratch (no cudaMalloc allowed) --------
__device__ float g_Q[Mc * Dc];
__device__ float g_K[Mc * Dc];
__device__ float g_V[Mc * Dc];
__device__ float g_C[Mc * Dc];
__device__ __nv_bfloat16 g_Ah[Mc * Dc];
__device__ __nv_bfloat16 g_Al[Mc * Dc];
__device__ __nv_bfloat16 g_Wh[Dc * Dc];   // transposed: [n][k]
__device__ __nv_bfloat16 g_Wl[Dc * Dc];   // transposed: [n][k]

// ============================================================
// Split fp32 -> bf16 hi/lo (elementwise, float4 vectorized)
// ============================================================
__global__ void split_kernel(const float* __restrict__ Asrc,
                             __nv_bfloat16* __restrict__ Ahi,
                             __nv_bfloat16* __restrict__ Alo,
                             int n4)
{
    int i = blockIdx.x * blockDim.x + threadIdx.x;
    if (i >= n4) return;
    float4 val = reinterpret_cast<const float4*>(Asrc)[i];
    __nv_bfloat16 hi0 = __float2bfloat16(val.x);
    __nv_bfloat16 hi1 = __float2bfloat16(val.y);
    __nv_bfloat16 hi2 = __float2bfloat16(val.z);
    __nv_bfloat16 hi3 = __float2bfloat16(val.w);
    __nv_bfloat16 lo0 = __float2bfloat16(val.x - __bfloat162float(hi0));
    __nv_bfloat16 lo1 = __float2bfloat16(val.y - __bfloat162float(hi1));
    __nv_bfloat16 lo2 = __float2bfloat16(val.z - __bfloat162float(hi2));
    __nv_bfloat16 lo3 = __float2bfloat16(val.w - __bfloat162float(hi3));
    __nv_bfloat162 hp0 = __halves2bfloat162(hi0, hi1);
    __nv_bfloat162 hp1 = __halves2bfloat162(hi2, hi3);
    __nv_bfloat162 lp0 = __halves2bfloat162(lo0, lo1);
    __nv_bfloat162 lp1 = __halves2bfloat162(lo2, lo3);
    reinterpret_cast<__nv_bfloat162*>(Ahi)[2 * i + 0] = hp0;
    reinterpret_cast<__nv_bfloat162*>(Ahi)[2 * i + 1] = hp1;
    reinterpret_cast<__nv_bfloat162*>(Alo)[2 * i + 0] = lp0;
    reinterpret_cast<__nv_bfloat162*>(Alo)[2 * i + 1] = lp1;
}

// ============================================================
// Split + transpose W[k][n] fp32 -> Th[n][k], Tl[n][k] bf16
// ============================================================
__global__ void splitT_kernel(const float* __restrict__ Wsrc,
                              __nv_bfloat16* __restrict__ Thi,
                              __nv_bfloat16* __restrict__ Tlo)
{
    __shared__ float tile[32][33];
    const int bn  = blockIdx.x * 32;
    const int bkk = blockIdx.y * 32;
    const int tx  = threadIdx.x;
    const int ty  = threadIdx.y;
#pragma unroll
    for (int i = 0; i < 32; i += 8) {
        tile[ty + i][tx] = Wsrc[(size_t)(bkk + ty + i) * Dc + bn + tx];
    }
    __syncthreads();
#pragma unroll
    for (int i = 0; i < 32; i += 8) {
        float xval = tile[tx][ty + i];
        __nv_bfloat16 hval = __float2bfloat16(xval);
        __nv_bfloat16 lval = __float2bfloat16(xval - __bfloat162float(hval));
        size_t oidx = (size_t)(bn + ty + i) * Dc + bkk + tx;
        Thi[oidx] = hval;
        Tlo[oidx] = lval;
    }
}

// ============================================================
// WMMA GEMM (split bf16, fp32 accumulate), no bias:
// C[M,N] = A[M,K] * T[N,K]^T ,  M=4096, N=K=1024
// 128x128 block, BK=32, 256 threads (8 warps 4x2), warp 32x64.
// smem row stride 48 bf16 (96B): 32B-aligned rows for wmma.
// ============================================================
#define BM 128
#define BN 128
#define BKg 32
#define SKs 48

__global__ __launch_bounds__(256)
void gemm_wmma_kernel(const __nv_bfloat16* __restrict__ Ahi,
                      const __nv_bfloat16* __restrict__ Alo,
                      const __nv_bfloat16* __restrict__ Whi,
                      const __nv_bfloat16* __restrict__ Wlo,
                      float* __restrict__ Cout)
{
    __shared__ __nv_bfloat16 sAh[BM * SKs];
    __shared__ __nv_bfloat16 sAl[BM * SKs];
    __shared__ __nv_bfloat16 sWh[BN * SKs];
    __shared__ __nv_bfloat16 sWl[BN * SKs];

    const int tid    = threadIdx.x;
    const int warp   = tid >> 5;
    const int warp_m = warp >> 1;   // 0..3
    const int warp_n = warp & 1;    // 0..1
    const int row0   = blockIdx.y * BM;
    const int col0   = blockIdx.x * BN;

    wmma::fragment<wmma::accumulator, 16, 16, 16, float> facc[2][4];
#pragma unroll
    for (int mt = 0; mt < 2; mt++) {
#pragma unroll
        for (int nt = 0; nt < 4; nt++) {
            wmma::fill_fragment(facc[mt][nt], 0.0f);
        }
    }

    for (int k0 = 0; k0 < Dc; k0 += BKg) {
        __syncthreads();
#pragma unroll
        for (int cc = 0; cc < 2; cc++) {
            const int idx  = tid + cc * 256;   // 0..511
            const int rr   = idx >> 2;         // 0..127
            const int kg   = (idx & 3) << 3;   // 0,8,16,24
            const int soff = rr * SKs + kg;
            const size_t goff_a = (size_t)(row0 + rr) * Dc + k0 + kg;
            const size_t goff_w = (size_t)(col0 + rr) * Dc + k0 + kg;
            *reinterpret_cast<uint4*>(&sAh[soff]) =
                *reinterpret_cast<const uint4*>(&Ahi[goff_a]);
            *reinterpret_cast<uint4*>(&sAl[soff]) =
                *reinterpret_cast<const uint4*>(&Alo[goff_a]);
            *reinterpret_cast<uint4*>(&sWh[soff]) =
                *reinterpret_cast<const uint4*>(&Whi[goff_w]);
            *reinterpret_cast<uint4*>(&sWl[soff]) =
                *reinterpret_cast<const uint4*>(&Wlo[goff_w]);
        }
        __syncthreads();

#pragma unroll
        for (int ks = 0; ks < BKg; ks += 16) {
            wmma::fragment<wmma::matrix_a, 16, 16, 16, __nv_bfloat16,
                           wmma::row_major> fah[2];
            wmma::fragment<wmma::matrix_a, 16, 16, 16, __nv_bfloat16,
                           wmma::row_major> fal[2];
#pragma unroll
            for (int mt = 0; mt < 2; mt++) {
                const int arow = warp_m * 32 + mt * 16;
                wmma::load_matrix_sync(fah[mt], &sAh[arow * SKs + ks], SKs);
                wmma::load_matrix_sync(fal[mt], &sAl[arow * SKs + ks], SKs);
            }
#pragma unroll
            for (int nt = 0; nt < 4; nt++) {
                const int wrow = warp_n * 64 + nt * 16;
                wmma::fragment<wmma::matrix_b, 16, 16, 16, __nv_bfloat16,
                               wmma::col_major> fwh;
                wmma::fragment<wmma::matrix_b, 16, 16, 16, __nv_bfloat16,
                               wmma::col_major> fwl;
                wmma::load_matrix_sync(fwh, &sWh[wrow * SKs + ks], SKs);
                wmma::load_matrix_sync(fwl, &sWl[wrow * SKs + ks], SKs);
#pragma unroll
                for (int mt = 0; mt < 2; mt++) {
                    wmma::mma_sync(facc[mt][nt], fah[mt], fwh, facc[mt][nt]);
                    wmma::mma_sync(facc[mt][nt], fah[mt], fwl, facc[mt][nt]);
                    wmma::mma_sync(facc[mt][nt], fal[mt], fwh, facc[mt][nt]);
                }
            }
        }
    }

#pragma unroll
    for (int mt = 0; mt < 2; mt++) {
#pragma unroll
        for (int nt = 0; nt < 4; nt++) {
            const int orow = row0 + warp_m * 32 + mt * 16;
            const int ocol = col0 + warp_n * 64 + nt * 16;
            wmma::store_matrix_sync(&Cout[(size_t)orow * Dc + ocol],
                                    facc[mt][nt], Dc, wmma::mem_row_major);
        }
    }
}

// ============================================================
// out[i] += bias[i mod Dc]   (final projection bias)
// ============================================================
__global__ void bias_add_kernel(float* __restrict__ out,
                                const float* __restrict__ bias)
{
    int i = blockIdx.x * blockDim.x + threadIdx.x;   // float4 index
    float4 val = reinterpret_cast<float4*>(out)[i];
    float4 bv  = reinterpret_cast<const float4*>(bias)[i & (Dc / 4 - 1)];
    val.x += bv.x;
    val.y += bv.y;
    val.z += bv.z;
    val.w += bv.w;
    reinterpret_cast<float4*>(out)[i] = val;
}

// ============================================================
// Causal flash attention, fp32. Adds Q/K/V projection biases
// at tile-load time (GEMM writes raw products).
// ============================================================
#define AQ 64
#define AJ 64

struct AttnSmem {
    float Qs[AQ][DKc + 1];
    float Ks[AJ][DKc + 1];
    float Ps[AQ][AJ + 1];
    float Vs[AJ][DKc];
};

__global__ __launch_bounds__(256, 3)
void attn_kernel(const float* __restrict__ bias_q,
                 const float* __restrict__ bias_k,
                 const float* __restrict__ bias_v)
{
    extern __shared__ char smem_raw[];
    AttnSmem& sm = *reinterpret_cast<AttnSmem*>(smem_raw);

    const int qt = blockIdx.x;
    const int hh = blockIdx.y;
    const int bb = blockIdx.z;
    const int q0 = qt * AQ;

    const int tid  = threadIdx.x;
    const int ty   = tid >> 4;
    const int tx   = tid & 15;
    const int qrow = ty * 4;
    const int jcol = tx * 4;

    const int lrow = tid >> 4;
    const int lcol = (tid & 15) * 4;

    const float4 bq4 = *reinterpret_cast<const float4*>(
        &bias_q[hh * DKc + lcol]);
    const float4 bk4 = *reinterpret_cast<const float4*>(
        &bias_k[hh * DKc + lcol]);
    const float4 bv4 = *reinterpret_cast<const float4*>(
        &bias_v[hh * DKc + lcol]);

#pragma unroll
    for (int it = 0; it < 4; it++) {
        const int rr = lrow + it * 16;
        float4 qv = *reinterpret_cast<const float4*>(
            &g_Q[(size_t)(bb * Sc + q0 + rr) * Dc + hh * DKc + lcol]);
        sm.Qs[rr][lcol + 0] = qv.x + bq4.x;
        sm.Qs[rr][lcol + 1] = qv.y + bq4.y;
        sm.Qs[rr][lcol + 2] = qv.z + bq4.z;
        sm.Qs[rr][lcol + 3] = qv.w + bq4.w;
    }

    float mrow[4];
    float lsum[4];
    float oacc[4][4];
#pragma unroll
    for (int i = 0; i < 4; i++) {
        mrow[i] = -1e30f;
        lsum[i] = 0.f;
#pragma unroll
        for (int j = 0; j < 4; j++) {
            oacc[i][j] = 0.f;
        }
    }

    for (int j0 = 0; j0 <= q0; j0 += AJ) {
        __syncthreads();
#pragma unroll
        for (int it = 0; it < 4; it++) {
            const int rr = lrow + it * 16;
            float4 kv = *reinterpret_cast<const float4*>(
                &g_K[(size_t)(bb * Sc + j0 + rr) * Dc + hh * DKc + lcol]);
            sm.Ks[rr][lcol + 0] = kv.x + bk4.x;
            sm.Ks[rr][lcol + 1] = kv.y + bk4.y;
            sm.Ks[rr][lcol + 2] = kv.z + bk4.z;
            sm.Ks[rr][lcol + 3] = kv.w + bk4.w;
            float4 vv = *reinterpret_cast<const float4*>(
                &g_V[(size_t)(bb * Sc + j0 + rr) * Dc + hh * DKc + lcol]);
            sm.Vs[rr][lcol + 0] = vv.x + bv4.x;
            sm.Vs[rr][lcol + 1] = vv.y + bv4.y;
            sm.Vs[rr][lcol + 2] = vv.z + bv4.z;
            sm.Vs[rr][lcol + 3] = vv.w + bv4.w;
        }
        __syncthreads();

        float sc[4][4];
#pragma unroll
        for (int i = 0; i < 4; i++) {
#pragma unroll
            for (int j = 0; j < 4; j++) {
                sc[i][j] = 0.f;
            }
        }

#pragma unroll 8
        for (int kk = 0; kk < DKc; kk++) {
            float qa0 = sm.Qs[qrow + 0][kk];
            float qa1 = sm.Qs[qrow + 1][kk];
            float qa2 = sm.Qs[qrow + 2][kk];
            float qa3 = sm.Qs[qrow + 3][kk];
            float kb0 = sm.Ks[jcol + 0][kk];
            float kb1 = sm.Ks[jcol + 1][kk];
            float kb2 = sm.Ks[jcol + 2][kk];
            float kb3 = sm.Ks[jcol + 3][kk];
            sc[0][0] = fmaf(qa0, kb0, sc[0][0]); sc[0][1] = fmaf(qa0, kb1, sc[0][1]);
            sc[0][2] = fmaf(qa0, kb2, sc[0][2]); sc[0][3] = fmaf(qa0, kb3, sc[0][3]);
            sc[1][0] = fmaf(qa1, kb0, sc[1][0]); sc[1][1] = fmaf(qa1, kb1, sc[1][1]);
            sc[1][2] = fmaf(qa1, kb2, sc[1][2]); sc[1][3] = fmaf(qa1, kb3, sc[1][3]);
            sc[2][0] = fmaf(qa2, kb0, sc[2][0]); sc[2][1] = fmaf(qa2, kb1, sc[2][1]);
            sc[2][2] = fmaf(qa2, kb2, sc[2][2]); sc[2][3] = fmaf(qa2, kb3, sc[2][3]);
            sc[3][0] = fmaf(qa3, kb0, sc[3][0]); sc[3][1] = fmaf(qa3, kb1, sc[3][1]);
            sc[3][2] = fmaf(qa3, kb2, sc[3][2]); sc[3][3] = fmaf(qa3, kb3, sc[3][3]);
        }

        const float scale = 0.125f;
#pragma unroll
        for (int i = 0; i < 4; i++) {
#pragma unroll
            for (int j = 0; j < 4; j++) {
                sc[i][j] *= scale;
            }
        }

        if (j0 == q0) {
#pragma unroll
            for (int i = 0; i < 4; i++) {
                const int gq = q0 + qrow + i;
#pragma unroll
                for (int j = 0; j < 4; j++) {
                    const int gk = j0 + jcol + j;
                    if (gk > gq) sc[i][j] = -1e9f;
                }
            }
        }

#pragma unroll
        for (int i = 0; i < 4; i++) {
            float mx = fmaxf(fmaxf(sc[i][0], sc[i][1]), fmaxf(sc[i][2], sc[i][3]));
#pragma unroll
            for (int off = 8; off >= 1; off >>= 1) {
                mx = fmaxf(mx, __shfl_xor_sync(0xffffffffu, mx, off, 16));
            }
            const float mnew  = fmaxf(mrow[i], mx);
            const float alpha = __expf(mrow[i] - mnew);
            float p0 = __expf(sc[i][0] - mnew);
            float p1 = __expf(sc[i][1] - mnew);
            float p2 = __expf(sc[i][2] - mnew);
            float p3 = __expf(sc[i][3] - mnew);
            float rs = p0 + p1 + p2 + p3;
#pragma unroll
            for (int off = 8; off >= 1; off >>= 1) {
                rs += __shfl_xor_sync(0xffffffffu, rs, off, 16);
            }
            lsum[i] = lsum[i] * alpha + rs;
            mrow[i] = mnew;
            oacc[i][0] *= alpha;
            oacc[i][1] *= alpha;
            oacc[i][2] *= alpha;
            oacc[i][3] *= alpha;
            sm.Ps[qrow + i][jcol + 0] = p0;
            sm.Ps[qrow + i][jcol + 1] = p1;
            sm.Ps[qrow + i][jcol + 2] = p2;
            sm.Ps[qrow + i][jcol + 3] = p3;
        }
        __syncthreads();

#pragma unroll 8
        for (int jj = 0; jj < AJ; jj++) {
            float pa0 = sm.Ps[qrow + 0][jj];
            float pa1 = sm.Ps[qrow + 1][jj];
            float pa2 = sm.Ps[qrow + 2][jj];
            float pa3 = sm.Ps[qrow + 3][jj];
            float4 vv = *reinterpret_cast<const float4*>(&sm.Vs[jj][jcol]);
            oacc[0][0] = fmaf(pa0, vv.x, oacc[0][0]); oacc[0][1] = fmaf(pa0, vv.y, oacc[0][1]);
            oacc[0][2] = fmaf(pa0, vv.z, oacc[0][2]); oacc[0][3] = fmaf(pa0, vv.w, oacc[0][3]);
            oacc[1][0] = fmaf(pa1, vv.x, oacc[1][0]); oacc[1][1] = fmaf(pa1, vv.y, oacc[1][1]);
            oacc[1][2] = fmaf(pa1, vv.z, oacc[1][2]); oacc[1][3] = fmaf(pa1, vv.w, oacc[1][3]);
            oacc[2][0] = fmaf(pa2, vv.x, oacc[2][0]); oacc[2][1] = fmaf(pa2, vv.y, oacc[2][1]);
            oacc[2][2] = fmaf(pa2, vv.z, oacc[2][2]); oacc[2][3] = fmaf(pa2, vv.w, oacc[2][3]);
            oacc[3][0] = fmaf(pa3, vv.x, oacc[3][0]); oacc[3][1] = fmaf(pa3, vv.y, oacc[3][1]);
            oacc[3][2] = fmaf(pa3, vv.z, oacc[3][2]); oacc[3][3] = fmaf(pa3, vv.w, oacc[3][3]);
        }
    }

#pragma unroll
    for (int i = 0; i < 4; i++) {
        const float inv = 1.0f / lsum[i];
        float4 ov;
        ov.x = oacc[i][0] * inv;
        ov.y = oacc[i][1] * inv;
        ov.z = oacc[i][2] * inv;
        ov.w = oacc[i][3] * inv;
        *reinterpret_cast<float4*>(
            &g_C[(size_t)(bb * Sc + q0 + qrow + i) * Dc + hh * DKc + jcol]) = ov;
    }
}

// ============================================================
// launch
// ============================================================
extern "C" void kernel_launch(void* const* d_in, const int* in_sizes, int n_in,
                              void* d_out, int out_size)
{
    (void)in_sizes; (void)n_in; (void)out_size;
    const float* in_q = (const float*)d_in[0];
    const float* in_k = (const float*)d_in[1];
    const float* in_v = (const float*)d_in[2];
    const float* w_q  = (const float*)d_in[4];
    const float* b_q  = (const float*)d_in[5];
    const float* w_k  = (const float*)d_in[6];
    const float* b_k  = (const float*)d_in[7];
    const float* w_v  = (const float*)d_in[8];
    const float* b_v  = (const float*)d_in[9];
    const float* w_o  = (const float*)d_in[10];
    const float* b_o  = (const float*)d_in[11];
    float* out = (float*)d_out;

    float* pQ;
    float* pK;
    float* pV;
    float* pC;
    __nv_bfloat16* pAh;
    __nv_bfloat16* pAl;
    __nv_bfloat16* pWh;
    __nv_bfloat16* pWl;
    cudaGetSymbolAddress((void**)&pQ, g_Q);
    cudaGetSymbolAddress((void**)&pK, g_K);
    cudaGetSymbolAddress((void**)&pV, g_V);
    cudaGetSymbolAddress((void**)&pC, g_C);
    cudaGetSymbolAddress((void**)&pAh, g_Ah);
    cudaGetSymbolAddress((void**)&pAl, g_Al);
    cudaGetSymbolAddress((void**)&pWh, g_Wh);
    cudaGetSymbolAddress((void**)&pWl, g_Wl);

    const int n4 = Mc * Dc / 4;
    dim3 tgrid(Dc / 32, Dc / 32);
    dim3 tblk(32, 8);
    dim3 ggrid(Dc / BN, Mc / BM);

    split_kernel<<<n4 / 256, 256>>>(in_q, pAh, pAl, n4);
    splitT_kernel<<<tgrid, tblk>>>(w_q, pWh, pWl);
    gemm_wmma_kernel<<<ggrid, 256>>>(pAh, pAl, pWh, pWl, pQ);

    split_kernel<<<n4 / 256, 256>>>(in_k, pAh, pAl, n4);
    splitT_kernel<<<tgrid, tblk>>>(w_k, pWh, pWl);
    gemm_wmma_kernel<<<ggrid, 256>>>(pAh, pAl, pWh, pWl, pK);

    split_kernel<<<n4 / 256, 256>>>(in_v, pAh, pAl, n4);
    splitT_kernel<<<tgrid, tblk>>>(w_v, pWh, pWl);
    gemm_wmma_kernel<<<ggrid, 256>>>(pAh, pAl, pWh, pWl, pV);

    cudaFuncSetAttribute(attn_kernel,
                         cudaFuncAttributeMaxDynamicSharedMemorySize,
                         (int)sizeof(AttnSmem));
    dim3 agrid(Sc / AQ, Hc, Bc);
    attn_kernel<<<agrid, 256, sizeof(AttnSmem)>>>(b_q, b_k, b_v);

    split_kernel<<<n4 / 256, 256>>>(pC, pAh, pAl, n4);
    splitT_kernel<<<tgrid, tblk>>>(w_o, pWh, pWl);
    gemm_wmma_kernel<<<ggrid, 256>>>(pAh, pAl, pWh, pWl, out);

    bias_add_kernel<<<Mc * Dc / 4 / 256, 256>>>(out, b_o);
}